// round 16
// baseline (speedup 1.0000x reference)
#include <cuda_runtime.h>
#include <cuda_fp16.h>
#include <cstdint>

// y[8192,4096] = x[8192,4096] @ Wq[4096,4096]^T + bias
// Wq = group-128 symmetric int4 fake-quant of W, stored fp16.
// GEMM: PERSISTENT cg2 tcgen05 kind::f16, supertile 512x256 per cluster pair,
// two 256x256 MMA tiles share each B stage, dedicated epilogue warps overlap
// TMEM drain with next-tile loads.
// R16 fix: epilogue warp -> TMEM subpartition mapping must be wid%4 (HW SMSP),
// not (wid-9). R15 scrambled output rows across subpartitions.

#define MROWS 8192
#define KDIM  4096
#define DOUT  4096

#define NSTAGES 4
#define KC      64                 // K halves per stage (= 128 B per row, SW128 atom)
#define STAGE_BYTES 49152          // A0 16KB + A1 16KB + B 16KB (fp16)
#define NPAIRS  74                 // 148 SMs / cluster 2
#define NTILES  256                // 16 m-supertiles x 16 n-supertiles
#define SOFF_FULL  16              // 4 x 8B
#define SOFF_EMPTY 64              // 4 x 8B
#define SOFF_EPIF  112
#define SOFF_EPID  120
#define SOFF_STG   2048
#define SMEM_BYTES (SOFF_STG + NSTAGES * STAGE_BYTES)  // 198656

// idesc kind::f16, fp16 inputs, f32 accum: dtype F32(1<<4) | (N/8)<<17 | (M/16)<<24
#define IDESC 0x10400010u

// tcgen05 is arch-SPECIFIC: gate off for the plain compute_103 PTX pass.
#if defined(__CUDA_ARCH_FEAT_SM103_ALL) || defined(__CUDA_ARCH_FEAT_SM101_ALL) || \
    defined(__CUDA_ARCH_FEAT_SM100_ALL) || defined(__CUDA_ARCH_SPECIFIC__)
#define TCGEN_OK 1
#else
#define TCGEN_OK 0
#endif

__device__ __half g_wq[16777216];   // 32 MiB: quantized W, fp16
__device__ __half g_xh[33554432];   // 64 MiB: x converted to fp16

// ---------------- helpers ----------------
__device__ __forceinline__ uint32_t s2u(const void* p) {
    uint32_t a;
    asm("{ .reg .u64 t; cvta.to.shared.u64 t, %1; cvt.u32.u64 %0, t; }" : "=r"(a) : "l"(p));
    return a;
}
__device__ __forceinline__ uint32_t pack_h2(float lo, float hi) {
    uint32_t u;
    asm("cvt.rn.f16x2.f32 %0, %1, %2;" : "=r"(u) : "f"(hi), "f"(lo));
    return u;
}
__device__ __forceinline__ uint32_t ctarank() {
    uint32_t r; asm("mov.u32 %0, %%cluster_ctarank;" : "=r"(r)); return r;
}
__device__ __forceinline__ void mbar_init(uint32_t a, uint32_t c) {
    asm volatile("mbarrier.init.shared.b64 [%0], %1;" :: "r"(a), "r"(c) : "memory");
}
__device__ __forceinline__ void mbar_wait(uint32_t a, uint32_t p) {
    asm volatile(
        "{\n\t.reg .pred P;\n"
        "W%=:\n\t"
        "mbarrier.try_wait.parity.acquire.cluster.shared::cta.b64 P, [%0], %1, 0x989680;\n\t"
        "@!P bra W%=;\n\t}\n"
        :: "r"(a), "r"(p) : "memory");
}
__device__ __forceinline__ void arrive_rank0(uint32_t a) {
    asm volatile(
        "{\n\t.reg .b32 r;\n\t"
        "mapa.shared::cluster.u32 r, %0, 0;\n\t"
        "mbarrier.arrive.shared::cluster.b64 _, [r];\n\t}\n"
        :: "r"(a) : "memory");
}
__device__ __forceinline__ void cp16(uint32_t dst, const void* src) {
    asm volatile("cp.async.cg.shared.global [%0], [%1], 16;" :: "r"(dst), "l"(src) : "memory");
}

#if TCGEN_OK
__device__ __forceinline__ void commit_mc(uint32_t bar) {
    asm volatile(
        "tcgen05.commit.cta_group::2.mbarrier::arrive::one.shared::cluster.multicast::cluster.b64 [%0], %1;"
        :: "r"(bar), "h"((uint16_t)3) : "memory");
}
__device__ __forceinline__ void mma_f16(uint32_t d, uint64_t ad, uint64_t bd, uint32_t en) {
    asm volatile(
        "{\n\t.reg .pred p;\n\t"
        "setp.ne.u32 p, %3, 0;\n\t"
        "tcgen05.mma.cta_group::2.kind::f16 [%0], %1, %2, %4, {%5,%5,%5,%5,%5,%5,%5,%5}, p;\n\t}\n"
        :: "r"(d), "l"(ad), "l"(bd), "r"(en), "r"(IDESC), "r"(0u) : "memory");
}
__device__ __forceinline__ void ldtm32(uint32_t* r, uint32_t a) {
    asm volatile(
        "tcgen05.ld.sync.aligned.32x32b.x32.b32 "
        "{%0,%1,%2,%3,%4,%5,%6,%7,%8,%9,%10,%11,%12,%13,%14,%15,"
        "%16,%17,%18,%19,%20,%21,%22,%23,%24,%25,%26,%27,%28,%29,%30,%31}, [%32];"
        : "=r"(r[0]),"=r"(r[1]),"=r"(r[2]),"=r"(r[3]),"=r"(r[4]),"=r"(r[5]),"=r"(r[6]),"=r"(r[7]),
          "=r"(r[8]),"=r"(r[9]),"=r"(r[10]),"=r"(r[11]),"=r"(r[12]),"=r"(r[13]),"=r"(r[14]),"=r"(r[15]),
          "=r"(r[16]),"=r"(r[17]),"=r"(r[18]),"=r"(r[19]),"=r"(r[20]),"=r"(r[21]),"=r"(r[22]),"=r"(r[23]),
          "=r"(r[24]),"=r"(r[25]),"=r"(r[26]),"=r"(r[27]),"=r"(r[28]),"=r"(r[29]),"=r"(r[30]),"=r"(r[31])
        : "r"(a));
}
#endif

__device__ __forceinline__ uint64_t smem_desc(uint32_t addr) {
    // SW128, version=1(Blackwell), SBO=64, LBO=1
    return ((uint64_t)2 << 61) | ((uint64_t)1 << 46) | ((uint64_t)64 << 32) |
           ((uint64_t)1 << 16) | ((uint64_t)(addr >> 4) & 0x3FFF);
}
__device__ __forceinline__ void cluster_sync() {
    asm volatile("barrier.cluster.arrive.aligned;" ::: "memory");
    asm volatile("barrier.cluster.wait.aligned;" ::: "memory");
}

// ---------------- kernel 1: fused prepass ----------------
// blocks [0,16384): group-128 int4 fake-quant of W -> fp16
// blocks [16384,32768): x fp32 -> fp16
__global__ __launch_bounds__(256) void prep_kernel(const float* __restrict__ w,
                                                   const float* __restrict__ x) {
    if (blockIdx.x < 16384) {
        int gw   = blockIdx.x * 8 + (threadIdx.x >> 5);  // global warp id = quant group
        int lane = threadIdx.x & 31;
        int row  = gw >> 5;
        int grp  = gw & 31;
        size_t base = (size_t)row * KDIM + grp * 128 + lane * 4;
        float4 v = *(const float4*)(w + base);
        float a = fmaxf(fmaxf(fabsf(v.x), fabsf(v.y)), fmaxf(fabsf(v.z), fabsf(v.w)));
        #pragma unroll
        for (int o = 16; o; o >>= 1) a = fmaxf(a, __shfl_xor_sync(0xFFFFFFFFu, a, o));
        float scale = __fdiv_rn(a, 7.0f);
        float ox = 0.f, oy = 0.f, oz = 0.f, ow = 0.f;
        if (scale > 0.0f) {
            ox = __fmul_rn(fminf(fmaxf(rintf(__fdiv_rn(v.x, scale)), -8.0f), 7.0f), scale);
            oy = __fmul_rn(fminf(fmaxf(rintf(__fdiv_rn(v.y, scale)), -8.0f), 7.0f), scale);
            oz = __fmul_rn(fminf(fmaxf(rintf(__fdiv_rn(v.z, scale)), -8.0f), 7.0f), scale);
            ow = __fmul_rn(fminf(fmaxf(rintf(__fdiv_rn(v.w, scale)), -8.0f), 7.0f), scale);
        }
        uint2 o; o.x = pack_h2(ox, oy); o.y = pack_h2(oz, ow);
        *(uint2*)((char*)g_wq + base * 2) = o;
    } else {
        size_t i = ((size_t)(blockIdx.x - 16384) * 256 + threadIdx.x) * 8;
        float4 v0 = *(const float4*)(x + i);
        float4 v1 = *(const float4*)(x + i + 4);
        uint4 o;
        o.x = pack_h2(v0.x, v0.y); o.y = pack_h2(v0.z, v0.w);
        o.z = pack_h2(v1.x, v1.y); o.w = pack_h2(v1.z, v1.w);
        *(uint4*)((char*)g_xh + i * 2) = o;
    }
}

// ---------------- kernel 2: persistent cg2 fp16 GEMM, 512x256 supertiles ----------------
__global__ __launch_bounds__(416, 1) __cluster_dims__(2, 1, 1)
void gemm_kernel(const float* __restrict__ bias, float* __restrict__ y) {
#if TCGEN_OK
    extern __shared__ char smem[];
    uint32_t sb = s2u(smem);
    int tid = threadIdx.x, wid = tid >> 5, lane = tid & 31;
    uint32_t rank = ctarank();
    int pid = (int)(blockIdx.x >> 1);
    int ntl = (NTILES - pid + NPAIRS - 1) / NPAIRS;   // tiles for this pair (3 or 4)

    if (wid == 8) {  // collective TMEM alloc: all 512 cols (two 256-col accumulators)
        asm volatile("tcgen05.alloc.cta_group::2.sync.aligned.shared::cta.b32 [%0], %1;"
                     :: "r"(sb), "r"(512u) : "memory");
    }
    if (tid == 0) {
        #pragma unroll
        for (int s = 0; s < NSTAGES; s++) {
            mbar_init(sb + SOFF_FULL  + 8 * s, 16);   // 8 loader warps x 2 CTAs
            mbar_init(sb + SOFF_EMPTY + 8 * s, 1);    // one commit arrival
        }
        mbar_init(sb + SOFF_EPIF, 1);                 // MMA-done commit (per tile)
        mbar_init(sb + SOFF_EPID, 8);                 // 4 epi warps x 2 CTAs
    }
    __syncthreads();
    uint32_t tmem;
    asm volatile("ld.shared.b32 %0, [%1];" : "=r"(tmem) : "r"(sb));
    cluster_sync();  // barriers visible cluster-wide before any cross-CTA arrive

    if (wid < 8) {
        // ------ loaders: continuous cp.async stream across all tiles ------
        int   bidx[4]; uint32_t sws[4];
        #pragma unroll
        for (int i = 0; i < 4; i++) {
            int idx = tid + i * 256;                   // sector id 0..1023
            int row = idx >> 3, sec = idx & 7;         // 128 rows x 8 x 16B
            bidx[i] = row * KDIM + sec * 8;            // element (half) offset
            uint32_t off = (uint32_t)(row * 128 + sec * 16);
            sws[i] = off ^ ((off >> 3) & 0x70);        // SW128 swizzle
        }
        const int NSt = ntl * 64;
        int stW = 0, phW = 1, stA = 0;
        #pragma unroll 1
        for (int gs = 0; gs < NSt + 2; gs++) {
            if (gs < NSt) {
                int tl = gs >> 6, kt = gs & 63;
                int sid = pid + tl * NPAIRS;
                int m0 = (sid >> 4) << 9, n0 = (sid & 15) << 8;
                const __half* A0b = g_xh + (size_t)(m0 + (int)rank * 128) * KDIM;
                const __half* A1b = A0b + (size_t)256 * KDIM;
                const __half* Bb  = g_wq + (size_t)(n0 + (int)rank * 128) * KDIM;
                int ko = kt * KC;
                mbar_wait(sb + SOFF_EMPTY + 8 * stW, phW);
                uint32_t S = sb + SOFF_STG + stW * STAGE_BYTES;
                #pragma unroll
                for (int i = 0; i < 4; i++) cp16(S +         sws[i], A0b + bidx[i] + ko);
                #pragma unroll
                for (int i = 0; i < 4; i++) cp16(S + 16384 + sws[i], A1b + bidx[i] + ko);
                #pragma unroll
                for (int i = 0; i < 4; i++) cp16(S + 32768 + sws[i], Bb  + bidx[i] + ko);
                if (++stW == NSTAGES) { stW = 0; phW ^= 1; }
            }
            asm volatile("cp.async.commit_group;" ::: "memory");
            if (gs >= 2) {
                asm volatile("cp.async.wait_group 2;" ::: "memory");
                __syncwarp();
                if (lane == 0) {
                    asm volatile("fence.proxy.async.shared::cta;" ::: "memory");
                    arrive_rank0(sb + SOFF_FULL + 8 * stA);
                }
                if (++stA == NSTAGES) stA = 0;
            }
        }
    } else if (wid == 8) {
        // ------ MMA issuer: leader CTA, lane 0 ------
        if (rank == 0 && lane == 0) {
            int st = 0, ph = 0;
            #pragma unroll 1
            for (int tl = 0; tl < ntl; tl++) {
                if (tl > 0) {  // previous tile's epilogue must finish reading TMEM
                    mbar_wait(sb + SOFF_EPID, (tl - 1) & 1);
                    asm volatile("tcgen05.fence::after_thread_sync;" ::: "memory");
                }
                #pragma unroll 1
                for (int kt = 0; kt < 64; kt++) {
                    mbar_wait(sb + SOFF_FULL + 8 * st, ph);
                    uint32_t S = sb + SOFF_STG + st * STAGE_BYTES;
                    uint64_t ad0 = smem_desc(S), ad1 = smem_desc(S + 16384),
                             bd  = smem_desc(S + 32768);
                    #pragma unroll
                    for (int k = 0; k < 4; k++) {   // 4 x K=16 fp16 steps per stage
                        uint32_t en = (uint32_t)(kt | k);
                        mma_f16(tmem,       ad0 + 2 * k, bd + 2 * k, en);
                        mma_f16(tmem + 256, ad1 + 2 * k, bd + 2 * k, en);
                    }
                    commit_mc(sb + SOFF_EMPTY + 8 * st);   // release stage, both CTAs
                    if (++st == NSTAGES) { st = 0; ph ^= 1; }
                }
                commit_mc(sb + SOFF_EPIF);                 // tile done -> both CTAs
            }
        }
    } else {
        // ------ epilogue: warps 9..12; HW subpartition = wid%4 ------
        int ew = wid & 3;                  // 9,10,11,12 -> subpartitions 1,2,3,0
        #pragma unroll 1
        for (int tl = 0; tl < ntl; tl++) {
            mbar_wait(sb + SOFF_EPIF, tl & 1);
            asm volatile("tcgen05.fence::after_thread_sync;" ::: "memory");
            int sid = pid + tl * NPAIRS;
            int m0 = (sid >> 4) << 9, n0 = (sid & 15) << 8;
            const float* bs = bias + n0;
            #pragma unroll
            for (int t = 0; t < 2; t++) {
                size_t row = (size_t)(m0 + t * 256 + (int)rank * 128 + ew * 32 + lane);
                float* yr = y + row * DOUT + n0;
                uint32_t tbase = tmem + (uint32_t)(t * 256);
                #pragma unroll
                for (int cb = 0; cb < 256; cb += 32) {
                    uint32_t d[32];
                    ldtm32(d, tbase + cb);
                    asm volatile("tcgen05.wait::ld.sync.aligned;" ::: "memory");
                    #pragma unroll
                    for (int c = 0; c < 32; c += 4) {
                        float4 bv = __ldg((const float4*)(bs + cb + c));
                        float4 o;
                        o.x = __uint_as_float(d[c + 0]) + bv.x;
                        o.y = __uint_as_float(d[c + 1]) + bv.y;
                        o.z = __uint_as_float(d[c + 2]) + bv.z;
                        o.w = __uint_as_float(d[c + 3]) + bv.w;
                        *(float4*)(yr + cb + c) = o;
                    }
                }
            }
            asm volatile("tcgen05.fence::before_thread_sync;" ::: "memory");
            __syncwarp();
            if (lane == 0) arrive_rank0(sb + SOFF_EPID);   // TMEM free for next tile
        }
    }

    __syncthreads();
    cluster_sync();
    if (wid == 8) {
        asm volatile("tcgen05.relinquish_alloc_permit.cta_group::2.sync.aligned;" ::: "memory");
        asm volatile("tcgen05.dealloc.cta_group::2.sync.aligned.b32 %0, %1;"
                     :: "r"(tmem), "r"(512u));
    }
    cluster_sync();
#else
    // ---- FFMA fallback for the non-'a' PTX pass (never runs on sm_103a). ----
    int tid = threadIdx.x;
    uint32_t rank = ctarank();
    int pid = (int)(blockIdx.x >> 1);
    for (int sid = pid; sid < NTILES; sid += NPAIRS) {
        int m0 = (sid >> 4) << 9, n0 = (sid & 15) << 8;
        int mbase = m0 + (int)rank * 256;
        for (int e = tid; e < 256 * 16; e += 416) {
            int r = e >> 4, cseg = e & 15;
            size_t row = (size_t)(mbase + r);
            float acc[16];
            #pragma unroll
            for (int j = 0; j < 16; j++) acc[j] = 0.0f;
            for (int k = 0; k < KDIM; k++) {
                float a = __half2float(g_xh[row * KDIM + k]);
                #pragma unroll
                for (int j = 0; j < 16; j++)
                    acc[j] += a * __half2float(g_wq[(size_t)(n0 + cseg * 16 + j) * KDIM + k]);
            }
            float* yr = y + row * DOUT + n0 + cseg * 16;
            #pragma unroll
            for (int j = 0; j < 16; j++) yr[j] = acc[j] + bias[n0 + cseg * 16 + j];
        }
    }
#endif
}

// ---------------- launch ----------------
extern "C" void kernel_launch(void* const* d_in, const int* in_sizes, int n_in,
                              void* d_out, int out_size) {
    const float* x = (const float*)d_in[0];
    const float* w = (const float*)d_in[1];
    const float* b = (const float*)d_in[2];
    float* y = (float*)d_out;

    prep_kernel<<<32768, 256>>>(w, x);

    cudaFuncSetAttribute(gemm_kernel, cudaFuncAttributeMaxDynamicSharedMemorySize, SMEM_BYTES);
    gemm_kernel<<<148, 416, SMEM_BYTES>>>(b, y);
}